// round 6
// baseline (speedup 1.0000x reference)
#include <cuda_runtime.h>

// Problem constants
#define TT    4096
#define EMB   1024
#define H2    512
#define G4    2048       // 4 * H2
#define NTAGS 5
#define START 3
#define STOP  4
#define NEGV  -10000.0f

// Recurrence: 64 CTAs per direction, 8 hidden units each, 1 warp per hidden
#define NCTA    64
#define HPER    8
#define HSTRIDE 2048     // padded floats per (dir,t): 64 slices * 32 (128B line each)
#define SENTB   0x7FC00000u

// -------------------- scratch (static device globals; no allocs) ------------
__device__ float d_G[2][TT * G4];          // input-gate preactivations (64 MB)
__device__ float d_h[2][TT * HSTRIDE];     // hidden states, line-padded (64 MB)
__device__ float d_feats[TT * 8];          // tag scores, padded stride 8

// -------------------- helpers ----------------------------------------------
__device__ __forceinline__ float4 ld_acq_v4(const float* p) {
    float4 v;
    asm volatile("ld.acquire.gpu.global.v4.f32 {%0,%1,%2,%3}, [%4];"
                 : "=f"(v.x), "=f"(v.y), "=f"(v.z), "=f"(v.w) : "l"(p) : "memory");
    return v;
}
__device__ __forceinline__ void st_rel_f32(float* p, float v) {
    asm volatile("st.release.gpu.global.f32 [%0], %1;" :: "l"(p), "f"(v) : "memory");
}
__device__ __forceinline__ float tanh_fast(float x) {
    float y;
    asm("tanh.approx.f32 %0, %1;" : "=f"(y) : "f"(x));
    return y;
}
__device__ __forceinline__ float sigmoid_fast(float x) {
    return fmaf(0.5f, tanh_fast(0.5f * x), 0.5f);
}

// -------------------- kernel: sentinel-init d_h ------------------------------
// d_h = 2*4096*2048 floats = 4,194,304 uint4
__global__ void k_init() {
    int i = blockIdx.x * blockDim.x + threadIdx.x;
    uint4 s; s.x = SENTB; s.y = SENTB; s.z = SENTB; s.w = SENTB;
    ((uint4*)d_h)[i] = s;
}

// -------------------- kernel: input GEMM  G = embed[sent] @ Wih^T + bias ----
// C tile 128x128, K tile 16, 256 threads, 8x8 blocking, double-buffered smem,
// embedding gather fused into the A load. dir==1 reads tokens in reverse.
__global__ __launch_bounds__(256) void k_gemm(
    const int*   __restrict__ sent, const float* __restrict__ embed,
    const float* __restrict__ Wf, const float* __restrict__ Wb,
    const float* __restrict__ bihf, const float* __restrict__ bhhf,
    const float* __restrict__ bihb, const float* __restrict__ bhhb) {
    int dir = blockIdx.z;
    const float* W  = dir ? Wb   : Wf;
    const float* b1 = dir ? bihb : bihf;
    const float* b2 = dir ? bhhb : bhhf;
    float* Gp = d_G[dir];

    __shared__ float As[2][16 * 128];
    __shared__ float Bs[2][16 * 128];

    int tid = threadIdx.x;
    int m0 = blockIdx.y * 128;
    int n0 = blockIdx.x * 128;
    int ty = tid >> 4, tx = tid & 15;

    int lrow[2], lkq[2];
    const float* Arow[2];
    const float* Brow[2];
#pragma unroll
    for (int h = 0; h < 2; h++) {
        int f = tid + h * 256;
        lrow[h] = f >> 2; lkq[h] = f & 3;
        int srcRow = m0 + lrow[h];
        if (dir) srcRow = TT - 1 - srcRow;
        int token = sent[srcRow];
        Arow[h] = embed + (size_t)token * EMB;
        Brow[h] = W + (size_t)(n0 + lrow[h]) * EMB;
    }

    float acc[8][8];
#pragma unroll
    for (int i = 0; i < 8; i++)
#pragma unroll
        for (int j = 0; j < 8; j++) acc[i][j] = 0.0f;

#pragma unroll
    for (int h = 0; h < 2; h++) {
        float4 va = *(const float4*)(Arow[h] + lkq[h] * 4);
        float4 vb = *(const float4*)(Brow[h] + lkq[h] * 4);
        As[0][(lkq[h]*4+0)*128 + lrow[h]] = va.x;
        As[0][(lkq[h]*4+1)*128 + lrow[h]] = va.y;
        As[0][(lkq[h]*4+2)*128 + lrow[h]] = va.z;
        As[0][(lkq[h]*4+3)*128 + lrow[h]] = va.w;
        Bs[0][(lkq[h]*4+0)*128 + lrow[h]] = vb.x;
        Bs[0][(lkq[h]*4+1)*128 + lrow[h]] = vb.y;
        Bs[0][(lkq[h]*4+2)*128 + lrow[h]] = vb.z;
        Bs[0][(lkq[h]*4+3)*128 + lrow[h]] = vb.w;
    }
    __syncthreads();

    for (int kt = 0; kt < EMB / 16; kt++) {
        int p = kt & 1;
        float4 va[2], vb[2];
        if (kt < EMB / 16 - 1) {
            int k0 = (kt + 1) * 16;
#pragma unroll
            for (int h = 0; h < 2; h++) {
                va[h] = *(const float4*)(Arow[h] + k0 + lkq[h] * 4);
                vb[h] = *(const float4*)(Brow[h] + k0 + lkq[h] * 4);
            }
        }
#pragma unroll
        for (int k = 0; k < 16; k++) {
            float a[8], bb[8];
#pragma unroll
            for (int i = 0; i < 8; i++) a[i]  = As[p][k * 128 + ty * 8 + i];
#pragma unroll
            for (int j = 0; j < 8; j++) bb[j] = Bs[p][k * 128 + tx * 8 + j];
#pragma unroll
            for (int i = 0; i < 8; i++)
#pragma unroll
                for (int j = 0; j < 8; j++) acc[i][j] += a[i] * bb[j];
        }
        if (kt < EMB / 16 - 1) {
            int q = 1 - p;
            __syncthreads();
#pragma unroll
            for (int h = 0; h < 2; h++) {
                As[q][(lkq[h]*4+0)*128 + lrow[h]] = va[h].x;
                As[q][(lkq[h]*4+1)*128 + lrow[h]] = va[h].y;
                As[q][(lkq[h]*4+2)*128 + lrow[h]] = va[h].z;
                As[q][(lkq[h]*4+3)*128 + lrow[h]] = va[h].w;
                Bs[q][(lkq[h]*4+0)*128 + lrow[h]] = vb[h].x;
                Bs[q][(lkq[h]*4+1)*128 + lrow[h]] = vb[h].y;
                Bs[q][(lkq[h]*4+2)*128 + lrow[h]] = vb[h].z;
                Bs[q][(lkq[h]*4+3)*128 + lrow[h]] = vb[h].w;
            }
            __syncthreads();
        }
    }

    float bias[8];
#pragma unroll
    for (int j = 0; j < 8; j++) {
        int n = n0 + tx * 8 + j;
        bias[j] = b1[n] + b2[n];
    }
#pragma unroll
    for (int i = 0; i < 8; i++) {
        int m = m0 + ty * 8 + i;
#pragma unroll
        for (int j = 0; j < 8; j++) {
            int n = n0 + tx * 8 + j;
            Gp[(size_t)m * G4 + n] = acc[i][j] + bias[j];
        }
    }
}

// -------------------- kernel: persistent LSTM recurrence --------------------
// 128 CTAs (64/dir), 256 threads. Warp w owns hidden unit hbase+w (all 4 gate
// rows). Lane s covers k in [16s,16s+16) for all 4 gates (64 weights/thread).
// Butterfly all-reduce -> lane 0 activation -> scalar st.release into the
// CTA's PRIVATE 128B line of d_h (no cross-CTA write sharing).
__global__ void __launch_bounds__(256, 1) k_recur(
    const float* __restrict__ Whh_f, const float* __restrict__ Whh_b,
    const float* __restrict__ h0, const float* __restrict__ c0) {
    int dir   = blockIdx.x >> 6;
    int slice = blockIdx.x & 63;
    int hbase = slice * HPER;
    const float* Whh = dir ? Whh_b : Whh_f;
    const float* Gd  = d_G[dir];
    float* hbuf = d_h[dir];

    int tid = threadIdx.x;
    int w = tid >> 5;            // warp -> hidden unit hbase+w
    int lane = tid & 31;         // k-chunk [16*lane, 16*lane+16)

    // weights: w4[g][q] = Whh[(g*H2 + hbase + w)*H2 + 16*lane + 4q .. +4)
    float4 w4[4][4];
#pragma unroll
    for (int g = 0; g < 4; g++) {
        const float* Wr = Whh + (size_t)(g * H2 + hbase + w) * H2 + 16 * lane;
#pragma unroll
        for (int q = 0; q < 4; q++) w4[g][q] = *(const float4*)(Wr + 4 * q);
    }

    __shared__ __align__(16) float sh[2][H2];

    float cj = 0.0f;
    if (lane == 0) cj = c0[dir * H2 + hbase + w];

    for (int t = 0; t < TT; t++) {
        // G(t) prefetch for this warp's hidden unit (lane 0, consumed at act)
        float gv0 = 0.f, gv1 = 0.f, gv2 = 0.f, gv3 = 0.f;
        if (lane == 0) {
            const float* Gt = Gd + (size_t)t * G4 + hbase + w;
            gv0 = Gt[0]; gv1 = Gt[H2]; gv2 = Gt[2 * H2]; gv3 = Gt[3 * H2];
        }

        // stage h(t-1) into double-buffered smem; poll the private lines
        float* dst = sh[t & 1];
        if (tid < 128) {
            if (t == 0) {
                *(float4*)(dst + tid * 4) =
                    *(const float4*)(h0 + dir * H2 + tid * 4);
            } else {
                const float* p = hbuf + (size_t)(t - 1) * HSTRIDE
                               + (tid >> 1) * 32 + (tid & 1) * 4;
                float4 v;
                do { v = ld_acq_v4(p); }
                while (__float_as_uint(v.x) == SENTB ||
                       __float_as_uint(v.y) == SENTB ||
                       __float_as_uint(v.z) == SENTB ||
                       __float_as_uint(v.w) == SENTB);
                *(float4*)(dst + tid * 4) = v;
            }
        }
        __syncthreads();

        // GEMV partials: 4 gates x 16 k-elems per lane
        const float4* sh4 = (const float4*)dst;
        float a0 = 0.f, a1 = 0.f, a2 = 0.f, a3 = 0.f;
#pragma unroll
        for (int q = 0; q < 4; q++) {
            float4 hv = sh4[4 * lane + q];
            a0 += w4[0][q].x*hv.x + w4[0][q].y*hv.y + w4[0][q].z*hv.z + w4[0][q].w*hv.w;
            a1 += w4[1][q].x*hv.x + w4[1][q].y*hv.y + w4[1][q].z*hv.z + w4[1][q].w*hv.w;
            a2 += w4[2][q].x*hv.x + w4[2][q].y*hv.y + w4[2][q].z*hv.z + w4[2][q].w*hv.w;
            a3 += w4[3][q].x*hv.x + w4[3][q].y*hv.y + w4[3][q].z*hv.z + w4[3][q].w*hv.w;
        }
        // butterfly all-reduce (all 4 gates land in every lane)
#pragma unroll
        for (int off = 16; off > 0; off >>= 1) {
            a0 += __shfl_xor_sync(0xffffffffu, a0, off);
            a1 += __shfl_xor_sync(0xffffffffu, a1, off);
            a2 += __shfl_xor_sync(0xffffffffu, a2, off);
            a3 += __shfl_xor_sync(0xffffffffu, a3, off);
        }

        // activation + private-line release store (lane 0 per warp)
        if (lane == 0) {
            float gi = a0 + gv0, gf = a1 + gv1, gg = a2 + gv2, go = a3 + gv3;
            cj = sigmoid_fast(gf) * cj + sigmoid_fast(gi) * tanh_fast(gg);
            float hj = sigmoid_fast(go) * tanh_fast(cj);
            st_rel_f32(hbuf + (size_t)t * HSTRIDE + slice * 32 + w, hj);
        }
    }
}

// -------------------- kernel: output projection feats = [hf|hb] @ Wout^T ----
__global__ void k_feats(const float* __restrict__ Wout,
                        const float* __restrict__ bout) {
    int t = blockIdx.x;
    int n = threadIdx.x >> 5;              // 5 warps -> 5 tags
    int lane = threadIdx.x & 31;
    const float* hf = d_h[0] + (size_t)t * HSTRIDE;
    const float* hb = d_h[1] + (size_t)(TT - 1 - t) * HSTRIDE;
    float s = 0.0f;
    const float* Wn = Wout + (size_t)n * (2 * H2);
#pragma unroll 4
    for (int k = lane; k < H2; k += 32) {
        int idx = ((k >> 3) << 5) + (k & 7);
        s += Wn[k] * hf[idx];
    }
#pragma unroll 4
    for (int k = lane; k < H2; k += 32) {
        int idx = ((k >> 3) << 5) + (k & 7);
        s += Wn[H2 + k] * hb[idx];
    }
#pragma unroll
    for (int off = 16; off > 0; off >>= 1) s += __shfl_xor_sync(0xffffffffu, s, off);
    if (lane == 0) d_feats[t * 8 + n] = s + bout[n];
}

// -------------------- kernel: Viterbi + backtrace (single CTA) --------------
// Lanes 0-4 each hold the full forward vector in registers and redundantly
// compute all 5 updates per step (no shuffles); own backpointer per lane.
__global__ void k_viterbi(const float* __restrict__ trans,
                          float* __restrict__ out, int out_size) {
    extern __shared__ float smem[];
    float* sfeat = smem;                                    // TT*8 floats
    unsigned char* sbp = (unsigned char*)(smem + TT * 8);   // TT*8 bytes

    int tid = threadIdx.x;
    const float4* d4 = (const float4*)d_feats;
    float4* s4 = (float4*)sfeat;
    for (int i = tid; i < (TT * 8) / 4; i += blockDim.x) s4[i] = d4[i];
    __syncthreads();

    if (tid < 32) {
        int lane = tid;
        int n = lane < NTAGS ? lane : NTAGS - 1;
        // full transition matrix in compile-time-indexed registers
        float t00=trans[0], t01=trans[1], t02=trans[2], t03=trans[3], t04=trans[4];
        float t10=trans[5], t11=trans[6], t12=trans[7], t13=trans[8], t14=trans[9];
        float t20=trans[10],t21=trans[11],t22=trans[12],t23=trans[13],t24=trans[14];
        float t30=trans[15],t31=trans[16],t32=trans[17],t33=trans[18],t34=trans[19];
        float t40=trans[20],t41=trans[21],t42=trans[22],t43=trans[23],t44=trans[24];
        // own row for backpointer
        float trn0 = trans[n*5+0], trn1 = trans[n*5+1], trn2 = trans[n*5+2],
              trn3 = trans[n*5+3], trn4 = trans[n*5+4];

        float f0 = (0 == START) ? 0.0f : NEGV;
        float f1 = (1 == START) ? 0.0f : NEGV;
        float f2 = (2 == START) ? 0.0f : NEGV;
        float f3 = (3 == START) ? 0.0f : NEGV;
        float f4 = (4 == START) ? 0.0f : NEGV;

        for (int t = 0; t < TT; t++) {
            float4 ft = *(const float4*)(sfeat + t * 8);
            float ft4 = sfeat[t * 8 + 4];

            // own backpointer (first-max-wins, matches argmax)
            float b = f0 + trn0; int bp = 0; float v;
            v = f1 + trn1; if (v > b) { b = v; bp = 1; }
            v = f2 + trn2; if (v > b) { b = v; bp = 2; }
            v = f3 + trn3; if (v > b) { b = v; bp = 3; }
            v = f4 + trn4; if (v > b) { b = v; bp = 4; }
            if (lane < NTAGS) sbp[t * 8 + lane] = (unsigned char)bp;

            // all 5 new forward values (redundant per lane, register-only)
            float m0 = fmaxf(fmaxf(fmaxf(f0+t00, f1+t01), fmaxf(f2+t02, f3+t03)), f4+t04);
            float m1 = fmaxf(fmaxf(fmaxf(f0+t10, f1+t11), fmaxf(f2+t12, f3+t13)), f4+t14);
            float m2 = fmaxf(fmaxf(fmaxf(f0+t20, f1+t21), fmaxf(f2+t22, f3+t23)), f4+t24);
            float m3 = fmaxf(fmaxf(fmaxf(f0+t30, f1+t31), fmaxf(f2+t32, f3+t33)), f4+t34);
            float m4 = fmaxf(fmaxf(fmaxf(f0+t40, f1+t41), fmaxf(f2+t42, f3+t43)), f4+t44);
            f0 = m0 + ft.x; f1 = m1 + ft.y; f2 = m2 + ft.z; f3 = m3 + ft.w; f4 = m4 + ft4;
        }

        if (lane == 0) {
            float fv[NTAGS] = {f0, f1, f2, f3, f4};
            float best = fv[0] + trans[STOP * NTAGS + 0];
            int bt = 0;
#pragma unroll
            for (int p = 1; p < NTAGS; p++) {
                float s = fv[p] + trans[STOP * NTAGS + p];
                if (s > best) { best = s; bt = p; }
            }
            if (out_size > 0) out[0] = best;
            int tag = bt;
            if (1 + (TT - 1) < out_size) out[1 + (TT - 1)] = (float)tag;
            for (int t = TT - 1; t >= 1; t--) {
                tag = sbp[t * 8 + tag];
                if (t < out_size) out[t] = (float)tag;
            }
        }
    }
}

// -------------------- launcher ----------------------------------------------
extern "C" void kernel_launch(void* const* d_in, const int* in_sizes, int n_in,
                              void* d_out, int out_size) {
    const int*   sent  = (const int*)d_in[0];
    const float* h0    = (const float*)d_in[1];
    const float* c0    = (const float*)d_in[2];
    const float* embed = (const float*)d_in[3];
    const float* Wih_f = (const float*)d_in[4];
    const float* Whh_f = (const float*)d_in[5];
    const float* bih_f = (const float*)d_in[6];
    const float* bhh_f = (const float*)d_in[7];
    const float* Wih_b = (const float*)d_in[8];
    const float* Whh_b = (const float*)d_in[9];
    const float* bih_b = (const float*)d_in[10];
    const float* bhh_b = (const float*)d_in[11];
    const float* Wout  = (const float*)d_in[12];
    const float* bout  = (const float*)d_in[13];
    const float* trans = (const float*)d_in[14];
    float* out = (float*)d_out;

    k_init<<<8192, 512>>>();
    dim3 gg(G4 / 128, TT / 128, 2);
    k_gemm<<<gg, 256>>>(sent, embed, Wih_f, Wih_b,
                        bih_f, bhh_f, bih_b, bhh_b);
    k_recur<<<2 * NCTA, 256>>>(Whh_f, Whh_b, h0, c0);
    k_feats<<<TT, 160>>>(Wout, bout);

    int vit_smem = TT * 8 * (int)sizeof(float) + TT * 8;   // 163840 B
    cudaFuncSetAttribute(k_viterbi, cudaFuncAttributeMaxDynamicSharedMemorySize,
                         vit_smem);
    k_viterbi<<<1, 128, vit_smem>>>(trans, out, out_size);
}

// round 7
// speedup vs baseline: 1.2367x; 1.2367x over previous
#include <cuda_runtime.h>

// Problem constants
#define TT    4096
#define EMB   1024
#define H2    512
#define G4    2048       // 4 * H2
#define NTAGS 5
#define START 3
#define STOP  4
#define NEGV  -10000.0f

// Recurrence: 64 CTAs per direction, 8 hidden units each, warp = hidden unit
#define NCTA   64
#define HPER   8
#define NREP   8         // h replication factor (poll-traffic spreading)
#define SENTB  0x7FC00000u

// -------------------- scratch (static device globals; no allocs) ------------
__device__ float d_G[2][TT * G4];               // input preactivations (64 MB)
__device__ float d_hrep[2][NREP][TT * H2];      // replicated hidden states (128 MB)
__device__ float d_feats[TT * 8];               // tag scores, stride 8

// -------------------- helpers ----------------------------------------------
__device__ __forceinline__ float4 ld_rlx_v4(const float* p) {
    float4 v;
    asm volatile("ld.relaxed.gpu.global.v4.f32 {%0,%1,%2,%3}, [%4];"
                 : "=f"(v.x), "=f"(v.y), "=f"(v.z), "=f"(v.w) : "l"(p) : "memory");
    return v;
}
__device__ __forceinline__ void st_rlx_f32(float* p, float v) {
    asm volatile("st.relaxed.gpu.global.f32 [%0], %1;" :: "l"(p), "f"(v) : "memory");
}
__device__ __forceinline__ float tanh_fast(float x) {
    float y;
    asm("tanh.approx.f32 %0, %1;" : "=f"(y) : "f"(x));
    return y;
}
__device__ __forceinline__ float sigmoid_fast(float x) {
    return fmaf(0.5f, tanh_fast(0.5f * x), 0.5f);
}

// -------------------- kernel: sentinel-init d_hrep ---------------------------
// 2*NREP*TT*H2 floats = 33,554,432 floats = 8,388,608 uint4
__global__ void k_init() {
    size_t i = (size_t)blockIdx.x * blockDim.x + threadIdx.x;
    uint4 s; s.x = SENTB; s.y = SENTB; s.z = SENTB; s.w = SENTB;
    ((uint4*)d_hrep)[i] = s;
}

// -------------------- kernel: input GEMM  G = embed[sent] @ Wih^T + bias ----
// C tile 128x128, K tile 16, 256 threads, 8x8 blocking, double-buffered smem,
// embedding gather fused into the A load. dir==1 reads tokens in reverse.
__global__ __launch_bounds__(256) void k_gemm(
    const int*   __restrict__ sent, const float* __restrict__ embed,
    const float* __restrict__ Wf, const float* __restrict__ Wb,
    const float* __restrict__ bihf, const float* __restrict__ bhhf,
    const float* __restrict__ bihb, const float* __restrict__ bhhb) {
    int dir = blockIdx.z;
    const float* W  = dir ? Wb   : Wf;
    const float* b1 = dir ? bihb : bihf;
    const float* b2 = dir ? bhhb : bhhf;
    float* Gp = d_G[dir];

    __shared__ float As[2][16 * 128];
    __shared__ float Bs[2][16 * 128];

    int tid = threadIdx.x;
    int m0 = blockIdx.y * 128;
    int n0 = blockIdx.x * 128;
    int ty = tid >> 4, tx = tid & 15;

    int lrow[2], lkq[2];
    const float* Arow[2];
    const float* Brow[2];
#pragma unroll
    for (int h = 0; h < 2; h++) {
        int f = tid + h * 256;
        lrow[h] = f >> 2; lkq[h] = f & 3;
        int srcRow = m0 + lrow[h];
        if (dir) srcRow = TT - 1 - srcRow;
        int token = sent[srcRow];
        Arow[h] = embed + (size_t)token * EMB;
        Brow[h] = W + (size_t)(n0 + lrow[h]) * EMB;
    }

    float acc[8][8];
#pragma unroll
    for (int i = 0; i < 8; i++)
#pragma unroll
        for (int j = 0; j < 8; j++) acc[i][j] = 0.0f;

#pragma unroll
    for (int h = 0; h < 2; h++) {
        float4 va = *(const float4*)(Arow[h] + lkq[h] * 4);
        float4 vb = *(const float4*)(Brow[h] + lkq[h] * 4);
        As[0][(lkq[h]*4+0)*128 + lrow[h]] = va.x;
        As[0][(lkq[h]*4+1)*128 + lrow[h]] = va.y;
        As[0][(lkq[h]*4+2)*128 + lrow[h]] = va.z;
        As[0][(lkq[h]*4+3)*128 + lrow[h]] = va.w;
        Bs[0][(lkq[h]*4+0)*128 + lrow[h]] = vb.x;
        Bs[0][(lkq[h]*4+1)*128 + lrow[h]] = vb.y;
        Bs[0][(lkq[h]*4+2)*128 + lrow[h]] = vb.z;
        Bs[0][(lkq[h]*4+3)*128 + lrow[h]] = vb.w;
    }
    __syncthreads();

    for (int kt = 0; kt < EMB / 16; kt++) {
        int p = kt & 1;
        float4 va[2], vb[2];
        if (kt < EMB / 16 - 1) {
            int k0 = (kt + 1) * 16;
#pragma unroll
            for (int h = 0; h < 2; h++) {
                va[h] = *(const float4*)(Arow[h] + k0 + lkq[h] * 4);
                vb[h] = *(const float4*)(Brow[h] + k0 + lkq[h] * 4);
            }
        }
#pragma unroll
        for (int k = 0; k < 16; k++) {
            float a[8], bb[8];
#pragma unroll
            for (int i = 0; i < 8; i++) a[i]  = As[p][k * 128 + ty * 8 + i];
#pragma unroll
            for (int j = 0; j < 8; j++) bb[j] = Bs[p][k * 128 + tx * 8 + j];
#pragma unroll
            for (int i = 0; i < 8; i++)
#pragma unroll
                for (int j = 0; j < 8; j++) acc[i][j] += a[i] * bb[j];
        }
        if (kt < EMB / 16 - 1) {
            int q = 1 - p;
            __syncthreads();
#pragma unroll
            for (int h = 0; h < 2; h++) {
                As[q][(lkq[h]*4+0)*128 + lrow[h]] = va[h].x;
                As[q][(lkq[h]*4+1)*128 + lrow[h]] = va[h].y;
                As[q][(lkq[h]*4+2)*128 + lrow[h]] = va[h].z;
                As[q][(lkq[h]*4+3)*128 + lrow[h]] = va[h].w;
                Bs[q][(lkq[h]*4+0)*128 + lrow[h]] = vb[h].x;
                Bs[q][(lkq[h]*4+1)*128 + lrow[h]] = vb[h].y;
                Bs[q][(lkq[h]*4+2)*128 + lrow[h]] = vb[h].z;
                Bs[q][(lkq[h]*4+3)*128 + lrow[h]] = vb[h].w;
            }
            __syncthreads();
        }
    }

    float bias[8];
#pragma unroll
    for (int j = 0; j < 8; j++) {
        int n = n0 + tx * 8 + j;
        bias[j] = b1[n] + b2[n];
    }
#pragma unroll
    for (int i = 0; i < 8; i++) {
        int m = m0 + ty * 8 + i;
#pragma unroll
        for (int j = 0; j < 8; j++) {
            int n = n0 + tx * 8 + j;
            Gp[(size_t)m * G4 + n] = acc[i][j] + bias[j];
        }
    }
}

// -------------------- kernel: persistent LSTM recurrence --------------------
// 128 CTAs (64/dir), 256 threads = 8 warps; warp w owns hidden unit hbase+w
// (all 4 gate rows, 64 weights/lane). Butterfly all-reduce leaves gate sums in
// every lane -> redundant activation -> lanes 0-7 store hj to 8 replicas in one
// warp STG. Consumer CTA polls replica (slice&7): sentinel-per-element, relaxed
// ops only, ONE __syncthreads per step.
__global__ void __launch_bounds__(256, 1) k_recur(
    const float* __restrict__ Whh_f, const float* __restrict__ Whh_b,
    const float* __restrict__ h0, const float* __restrict__ c0) {
    int dir   = blockIdx.x >> 6;
    int slice = blockIdx.x & 63;
    int hbase = slice * HPER;
    const float* Whh = dir ? Whh_b : Whh_f;
    const float* Gd  = d_G[dir];
    float* hrep = d_hrep[dir][0];            // replica r at offset r*TT*H2
    const float* hpoll = d_hrep[dir][slice & 7];

    int tid = threadIdx.x;
    int w = tid >> 5;            // warp -> hidden unit hbase+w
    int lane = tid & 31;         // k-chunk [16*lane, 16*lane+16)

    // weights: w4[g][q] = Whh[(g*H2 + hbase + w)*H2 + 16*lane + 4q ..+4)
    float4 w4[4][4];
#pragma unroll
    for (int g = 0; g < 4; g++) {
        const float* Wr = Whh + (size_t)(g * H2 + hbase + w) * H2 + 16 * lane;
#pragma unroll
        for (int q = 0; q < 4; q++) w4[g][q] = *(const float4*)(Wr + 4 * q);
    }

    __shared__ __align__(16) float sh[2][H2];

    // all lanes carry identical state (redundant activation)
    float cj = c0[dir * H2 + hbase + w];
    float gv0, gv1, gv2, gv3;
    {
        const float* Gt = Gd + hbase + w;
        gv0 = Gt[0]; gv1 = Gt[H2]; gv2 = Gt[2 * H2]; gv3 = Gt[3 * H2];
    }

    // stage h(-1) = h0
    if (tid < 128)
        *(float4*)(sh[0] + tid * 4) = *(const float4*)(h0 + dir * H2 + tid * 4);
    __syncthreads();

    bool is_poller = (tid < 128) && ((tid >> 1) != slice);

    for (int t = 0; t < TT; t++) {
        // GEMV on sh[t&1]
        const float4* sh4 = (const float4*)sh[t & 1];
        float a0 = 0.f, a1 = 0.f, a2 = 0.f, a3 = 0.f;
#pragma unroll
        for (int q = 0; q < 4; q++) {
            float4 hv = sh4[4 * lane + q];
            a0 += w4[0][q].x*hv.x + w4[0][q].y*hv.y + w4[0][q].z*hv.z + w4[0][q].w*hv.w;
            a1 += w4[1][q].x*hv.x + w4[1][q].y*hv.y + w4[1][q].z*hv.z + w4[1][q].w*hv.w;
            a2 += w4[2][q].x*hv.x + w4[2][q].y*hv.y + w4[2][q].z*hv.z + w4[2][q].w*hv.w;
            a3 += w4[3][q].x*hv.x + w4[3][q].y*hv.y + w4[3][q].z*hv.z + w4[3][q].w*hv.w;
        }
#pragma unroll
        for (int off = 16; off > 0; off >>= 1) {
            a0 += __shfl_xor_sync(0xffffffffu, a0, off);
            a1 += __shfl_xor_sync(0xffffffffu, a1, off);
            a2 += __shfl_xor_sync(0xffffffffu, a2, off);
            a3 += __shfl_xor_sync(0xffffffffu, a3, off);
        }

        // redundant activation in all lanes
        float gi = a0 + gv0, gf = a1 + gv1, gg = a2 + gv2, go = a3 + gv3;
        cj = sigmoid_fast(gf) * cj + sigmoid_fast(gi) * tanh_fast(gg);
        float hj = sigmoid_fast(go) * tanh_fast(cj);

        // publish: lanes 0-7 store hj to the 8 replicas (one warp STG, 8 lines)
        if (lane < NREP)
            st_rlx_f32(hrep + (size_t)lane * (TT * H2) + (size_t)t * H2 + hbase + w, hj);
        // pre-stage own slice for next step's smem buffer
        if (lane == 0) sh[(t + 1) & 1][hbase + w] = hj;

        // prefetch next G (all lanes, broadcast addresses)
        if (t + 1 < TT) {
            const float* Gn = Gd + (size_t)(t + 1) * G4 + hbase + w;
            gv0 = Gn[0]; gv1 = Gn[H2]; gv2 = Gn[2 * H2]; gv3 = Gn[3 * H2];

            // poll h(t) of other slices from my replica; sentinel per element
            if (is_poller) {
                const float* p = hpoll + (size_t)t * H2 + tid * 4;
                float4 v;
                do { v = ld_rlx_v4(p); }
                while (__float_as_uint(v.x) == SENTB ||
                       __float_as_uint(v.y) == SENTB ||
                       __float_as_uint(v.z) == SENTB ||
                       __float_as_uint(v.w) == SENTB);
                *(float4*)(sh[(t + 1) & 1] + tid * 4) = v;
            }
            __syncthreads();
        }
    }
}

// -------------------- kernel: output projection feats = [hf|hb] @ Wout^T ----
__global__ void k_feats(const float* __restrict__ Wout,
                        const float* __restrict__ bout) {
    int t = blockIdx.x;
    int n = threadIdx.x >> 5;              // 5 warps -> 5 tags
    int lane = threadIdx.x & 31;
    const float* hf = d_hrep[0][0] + (size_t)t * H2;
    const float* hb = d_hrep[1][0] + (size_t)(TT - 1 - t) * H2;
    float s = 0.0f;
    const float* Wn = Wout + (size_t)n * (2 * H2);
#pragma unroll 4
    for (int k = lane; k < H2; k += 32) s += Wn[k] * hf[k];
#pragma unroll 4
    for (int k = lane; k < H2; k += 32) s += Wn[H2 + k] * hb[k];
#pragma unroll
    for (int off = 16; off > 0; off >>= 1) s += __shfl_xor_sync(0xffffffffu, s, off);
    if (lane == 0) d_feats[t * 8 + n] = s + bout[n];
}

// -------------------- kernel: Viterbi + backtrace (single CTA) --------------
__global__ void k_viterbi(const float* __restrict__ trans,
                          float* __restrict__ out, int out_size) {
    extern __shared__ float smem[];
    float* sfeat = smem;                                    // TT*8 floats
    unsigned char* sbp = (unsigned char*)(smem + TT * 8);   // TT*8 bytes

    int tid = threadIdx.x;
    const float4* d4 = (const float4*)d_feats;
    float4* s4 = (float4*)sfeat;
    for (int i = tid; i < (TT * 8) / 4; i += blockDim.x) s4[i] = d4[i];
    __syncthreads();

    if (tid < 32) {
        int lane = tid;
        int n = lane < NTAGS ? lane : NTAGS - 1;
        float t00=trans[0], t01=trans[1], t02=trans[2], t03=trans[3], t04=trans[4];
        float t10=trans[5], t11=trans[6], t12=trans[7], t13=trans[8], t14=trans[9];
        float t20=trans[10],t21=trans[11],t22=trans[12],t23=trans[13],t24=trans[14];
        float t30=trans[15],t31=trans[16],t32=trans[17],t33=trans[18],t34=trans[19];
        float t40=trans[20],t41=trans[21],t42=trans[22],t43=trans[23],t44=trans[24];
        float trn0 = trans[n*5+0], trn1 = trans[n*5+1], trn2 = trans[n*5+2],
              trn3 = trans[n*5+3], trn4 = trans[n*5+4];

        float f0 = (0 == START) ? 0.0f : NEGV;
        float f1 = (1 == START) ? 0.0f : NEGV;
        float f2 = (2 == START) ? 0.0f : NEGV;
        float f3 = (3 == START) ? 0.0f : NEGV;
        float f4 = (4 == START) ? 0.0f : NEGV;

        for (int t = 0; t < TT; t++) {
            float4 ft = *(const float4*)(sfeat + t * 8);
            float ft4 = sfeat[t * 8 + 4];

            float b = f0 + trn0; int bp = 0; float v;
            v = f1 + trn1; if (v > b) { b = v; bp = 1; }
            v = f2 + trn2; if (v > b) { b = v; bp = 2; }
            v = f3 + trn3; if (v > b) { b = v; bp = 3; }
            v = f4 + trn4; if (v > b) { b = v; bp = 4; }
            if (lane < NTAGS) sbp[t * 8 + lane] = (unsigned char)bp;

            float m0 = fmaxf(fmaxf(fmaxf(f0+t00, f1+t01), fmaxf(f2+t02, f3+t03)), f4+t04);
            float m1 = fmaxf(fmaxf(fmaxf(f0+t10, f1+t11), fmaxf(f2+t12, f3+t13)), f4+t14);
            float m2 = fmaxf(fmaxf(fmaxf(f0+t20, f1+t21), fmaxf(f2+t22, f3+t23)), f4+t24);
            float m3 = fmaxf(fmaxf(fmaxf(f0+t30, f1+t31), fmaxf(f2+t32, f3+t33)), f4+t34);
            float m4 = fmaxf(fmaxf(fmaxf(f0+t40, f1+t41), fmaxf(f2+t42, f3+t43)), f4+t44);
            f0 = m0 + ft.x; f1 = m1 + ft.y; f2 = m2 + ft.z; f3 = m3 + ft.w; f4 = m4 + ft4;
        }

        if (lane == 0) {
            float fv[NTAGS] = {f0, f1, f2, f3, f4};
            float best = fv[0] + trans[STOP * NTAGS + 0];
            int bt = 0;
#pragma unroll
            for (int p = 1; p < NTAGS; p++) {
                float s = fv[p] + trans[STOP * NTAGS + p];
                if (s > best) { best = s; bt = p; }
            }
            if (out_size > 0) out[0] = best;
            int tag = bt;
            if (1 + (TT - 1) < out_size) out[1 + (TT - 1)] = (float)tag;
            for (int t = TT - 1; t >= 1; t--) {
                tag = sbp[t * 8 + tag];
                if (t < out_size) out[t] = (float)tag;
            }
        }
    }
}

// -------------------- launcher ----------------------------------------------
extern "C" void kernel_launch(void* const* d_in, const int* in_sizes, int n_in,
                              void* d_out, int out_size) {
    const int*   sent  = (const int*)d_in[0];
    const float* h0    = (const float*)d_in[1];
    const float* c0    = (const float*)d_in[2];
    const float* embed = (const float*)d_in[3];
    const float* Wih_f = (const float*)d_in[4];
    const float* Whh_f = (const float*)d_in[5];
    const float* bih_f = (const float*)d_in[6];
    const float* bhh_f = (const float*)d_in[7];
    const float* Wih_b = (const float*)d_in[8];
    const float* Whh_b = (const float*)d_in[9];
    const float* bih_b = (const float*)d_in[10];
    const float* bhh_b = (const float*)d_in[11];
    const float* Wout  = (const float*)d_in[12];
    const float* bout  = (const float*)d_in[13];
    const float* trans = (const float*)d_in[14];
    float* out = (float*)d_out;

    // sentinel-init all replicas: 2*NREP*TT*H2/4 uint4 = 8,388,608
    k_init<<<16384, 512>>>();
    dim3 gg(G4 / 128, TT / 128, 2);
    k_gemm<<<gg, 256>>>(sent, embed, Wih_f, Wih_b,
                        bih_f, bhh_f, bih_b, bhh_b);
    k_recur<<<2 * NCTA, 256>>>(Whh_f, Whh_b, h0, c0);
    k_feats<<<TT, 160>>>(Wout, bout);

    int vit_smem = TT * 8 * (int)sizeof(float) + TT * 8;   // 163840 B
    cudaFuncSetAttribute(k_viterbi, cudaFuncAttributeMaxDynamicSharedMemorySize,
                         vit_smem);
    k_viterbi<<<1, 128, vit_smem>>>(trans, out, out_size);
}